// round 15
// baseline (speedup 1.0000x reference)
#include <cuda_runtime.h>
#include <cuda_fp16.h>
#include <cstdint>

// Problem constants
#define BB 8
#define NN 1024
#define DD 768
#define HH 12
#define HD 64
#define MM (BB * NN)   // 8192 rows
#define SCALEQ 0.18033688011112042591f   // 0.125 * log2(e), applied post-MMA

// ---------------------------------------------------------------------------
// Scratch (__device__ globals; no allocation allowed)
// ---------------------------------------------------------------------------
__device__ __half g_x[MM * DD];                   // x single
__device__ __half g_q[MM * DD];                   // q single (UNSCALED)
__device__ __half g_k[MM * DD];                   // k single
__device__ __half g_vt[MM * DD];                  // v single, transposed [(b*768+d)][n]
__device__ __half g_c[MM * DD];                   // attention output single
__device__ __half g_w[4 * DD * DD];               // weights single, transposed [n][k]

// ---------------------------------------------------------------------------
// PTX helpers
// ---------------------------------------------------------------------------
__device__ __forceinline__ uint32_t s2u(const void* p) {
    uint32_t a;
    asm("{ .reg .u64 t; cvta.to.shared.u64 t, %1; cvt.u32.u64 %0, t; }"
        : "=r"(a) : "l"(p));
    return a;
}
__device__ __forceinline__ void cp16(uint32_t dst, const void* src) {
    asm volatile("cp.async.cg.shared.global [%0], [%1], 16;" :: "r"(dst), "l"(src));
}
#define CP_COMMIT() asm volatile("cp.async.commit_group;" ::: "memory")
#define CP_WAIT0()  asm volatile("cp.async.wait_group 0;" ::: "memory")
#define CP_WAIT1()  asm volatile("cp.async.wait_group 1;" ::: "memory")

__device__ __forceinline__ void ldm_x4(uint32_t* r, uint32_t addr) {
    asm volatile("ldmatrix.sync.aligned.m8n8.x4.shared.b16 {%0,%1,%2,%3}, [%4];"
                 : "=r"(r[0]), "=r"(r[1]), "=r"(r[2]), "=r"(r[3]) : "r"(addr));
}
__device__ __forceinline__ void mma16816(float* c, const uint32_t* a, const uint32_t* b) {
    asm volatile(
        "mma.sync.aligned.m16n8k16.row.col.f32.f16.f16.f32 "
        "{%0,%1,%2,%3}, {%4,%5,%6,%7}, {%8,%9}, {%0,%1,%2,%3};"
        : "+f"(c[0]), "+f"(c[1]), "+f"(c[2]), "+f"(c[3])
        : "r"(a[0]), "r"(a[1]), "r"(a[2]), "r"(a[3]), "r"(b[0]), "r"(b[1]));
}
__device__ __forceinline__ float ex2(float x) {
    float y;
    asm("ex2.approx.ftz.f32 %0, %1;" : "=f"(y) : "f"(x));
    return y;
}
// pack two fp32 into f16x2 in ONE instruction.  First asm source = HIGH half.
__device__ __forceinline__ uint32_t cvt2h(float lo, float hi) {
    uint32_t r;
    asm("cvt.rn.f16x2.f32 %0, %1, %2;" : "=r"(r) : "f"(hi), "f"(lo));
    return r;
}
// packed fp16x2 exp2: one MUFU op for two values
__device__ __forceinline__ uint32_t h2ex2(uint32_t a) {
    uint32_t r;
    asm("ex2.approx.f16x2 %0, %1;" : "=r"(r) : "r"(a));
    return r;
}

// swizzled offset within a tile of 128B rows (8 16B units per row)
__device__ __forceinline__ uint32_t swz8o(int r, int u) {
    return (uint32_t)(r * 128 + ((u ^ (r & 7)) << 4));
}

// ---------------------------------------------------------------------------
// Conversions
// ---------------------------------------------------------------------------
__global__ __launch_bounds__(256) void convert_half_kernel(
    const float* __restrict__ src, __half* __restrict__ dst) {
    const int idx = blockIdx.x * 256 + threadIdx.x;
    const float4 v0 = *reinterpret_cast<const float4*>(&src[idx * 8]);
    const float4 v1 = *reinterpret_cast<const float4*>(&src[idx * 8 + 4]);
    uint4 p;
    p.x = cvt2h(v0.x, v0.y);
    p.y = cvt2h(v0.z, v0.w);
    p.z = cvt2h(v1.x, v1.y);
    p.w = cvt2h(v1.z, v1.w);
    reinterpret_cast<uint4*>(dst)[idx] = p;
}

__global__ __launch_bounds__(256) void convert_wt_kernel(
    const float* __restrict__ Wq, const float* __restrict__ Wk,
    const float* __restrict__ Wv, const float* __restrict__ Wo,
    __half* __restrict__ dw) {
    __shared__ float tile[64][65];
    const int z = blockIdx.z;
    const float* W = (z == 0) ? Wq : (z == 1) ? Wk : (z == 2) ? Wv : Wo;
    __half* ow = dw + (size_t)z * DD * DD;
    const int k0 = blockIdx.x * 64;
    const int n0 = blockIdx.y * 64;
    const int tid = threadIdx.x;
#pragma unroll
    for (int t = tid; t < 64 * 16; t += 256) {
        const int i = t >> 4;
        const int j4 = (t & 15) * 4;
        const float4 w = *reinterpret_cast<const float4*>(&W[(k0 + i) * DD + n0 + j4]);
        tile[i][j4 + 0] = w.x;
        tile[i][j4 + 1] = w.y;
        tile[i][j4 + 2] = w.z;
        tile[i][j4 + 3] = w.w;
    }
    __syncthreads();
#pragma unroll
    for (int t = tid; t < 64 * 8; t += 256) {
        const int nl = t >> 3;
        const int kin = (t & 7) * 8;
        uint4 pw;
        uint32_t* wp = &pw.x;
#pragma unroll
        for (int m = 0; m < 4; m++)
            wp[m] = cvt2h(tile[kin + m * 2][nl], tile[kin + m * 2 + 1][nl]);
        reinterpret_cast<uint4*>(ow)[((size_t)(n0 + nl) * DD + k0 + kin) >> 3] = pw;
    }
}

// ---------------------------------------------------------------------------
// fp16 single GEMM: C = A @ B^T (+bias).
// CTA tile 128m x 128n, 8 warps (2m x 4n), warp tile 64x32.  KT=64,
// 2-stage cp.async pipeline.  Stage: A 16K | B 16K = 32K; x2 = 64K.
// Epilogue modes: 0 fp32+bias; 2 transposed half single; 3 half single.
// ---------------------------------------------------------------------------
#define KT 64
#define GEMM_STAGE 32768
#define GEMM_SMEM (2 * GEMM_STAGE)   // 65536

__device__ __forceinline__ void gemm_issue(
    uint32_t sb, const __half* A, const __half* B,
    int mBase, int nBase, int kBase, int tid) {
#pragma unroll
    for (int i = 0; i < 4; i++) {   // A: 1024 units (128 r x 8 u)
        const int t = tid + i * 256;
        const int r = (t >> 3) & 127, u = t & 7;
        cp16(sb + swz8o(r, u), A + (size_t)(mBase + r) * DD + kBase + u * 8);
    }
#pragma unroll
    for (int i = 0; i < 4; i++) {   // B: 1024 units (128 r x 8 u)
        const int t = tid + i * 256;
        const int r = (t >> 3) & 127, u = t & 7;
        cp16(sb + 16384 + swz8o(r, u),
             B + (size_t)(nBase + r) * DD + kBase + u * 8);
    }
}

__device__ __forceinline__ void gemm_body(
    const __half* __restrict__ A, const __half* __restrict__ B,
    const float* __restrict__ bias, int mode,
    float* __restrict__ C, __half* __restrict__ Oh) {
    extern __shared__ char smem[];
    const uint32_t sbase = s2u(smem);

    const int tid = threadIdx.x;
    const int wid = tid >> 5;
    const int lane = tid & 31;
    const int m0 = (wid >> 2) * 64;
    const int n0 = (wid & 3) * 32;
    const int mBase = blockIdx.y * 128;
    const int nBase = blockIdx.x * 128;

    float acc[4][4][4];
#pragma unroll
    for (int i = 0; i < 4; i++)
#pragma unroll
        for (int j = 0; j < 4; j++)
#pragma unroll
            for (int q = 0; q < 4; q++) acc[i][j][q] = 0.0f;

    gemm_issue(sbase, A, B, mBase, nBase, 0, tid);
    CP_COMMIT();
    gemm_issue(sbase + GEMM_STAGE, A, B, mBase, nBase, KT, tid);
    CP_COMMIT();

    const int a_r = lane & 15;
    const int a_uh = lane >> 4;
    const int b_r = ((lane >> 4) & 1) * 8 + (lane & 7);
    const int b_uh = (lane >> 3) & 1;

    const int NKT = DD / KT;   // 12
    for (int kt = 0; kt < NKT; kt++) {
        CP_WAIT1();
        __syncthreads();
        const uint32_t st = sbase + (kt & 1) * GEMM_STAGE;
#pragma unroll
        for (int ks = 0; ks < 4; ks++) {
            const int ua = ks * 2 + a_uh;
            const int ub = ks * 2 + b_uh;
            uint32_t a4[4][4];
#pragma unroll
            for (int fm = 0; fm < 4; fm++)
                ldm_x4(a4[fm], st + swz8o(m0 + fm * 16 + a_r, ua));
#pragma unroll
            for (int fn2 = 0; fn2 < 2; fn2++) {
                uint32_t b4[4];
                ldm_x4(b4, st + 16384 + swz8o(n0 + fn2 * 16 + b_r, ub));
#pragma unroll
                for (int fm = 0; fm < 4; fm++) {
#pragma unroll
                    for (int hf = 0; hf < 2; hf++)
                        mma16816(acc[fm][fn2 * 2 + hf], a4[fm], &b4[hf * 2]);
                }
            }
        }
        __syncthreads();
        if (kt + 2 < NKT)
            gemm_issue(sbase + (kt & 1) * GEMM_STAGE, A, B,
                       mBase, nBase, (kt + 2) * KT, tid);
        CP_COMMIT();
    }

    const int row_l = lane >> 2;
    const int col_l = (lane & 3) * 2;
#pragma unroll
    for (int fn = 0; fn < 4; fn++) {
        const int col = nBase + n0 + fn * 8 + col_l;
        const float2 bv = *reinterpret_cast<const float2*>(&bias[col]);
#pragma unroll
        for (int fm = 0; fm < 4; fm++) {
            const int row = mBase + m0 + fm * 16 + row_l;
            float v0 = acc[fm][fn][0] + bv.x;
            float v1 = acc[fm][fn][1] + bv.y;
            float v2 = acc[fm][fn][2] + bv.x;
            float v3 = acc[fm][fn][3] + bv.y;
            if (mode == 0) {
                *reinterpret_cast<float2*>(&C[(size_t)row * DD + col]) = make_float2(v0, v1);
                *reinterpret_cast<float2*>(&C[(size_t)(row + 8) * DD + col]) = make_float2(v2, v3);
            } else if (mode == 3) {
                *reinterpret_cast<uint32_t*>(&Oh[(size_t)row * DD + col]) = cvt2h(v0, v1);
                *reinterpret_cast<uint32_t*>(&Oh[(size_t)(row + 8) * DD + col]) = cvt2h(v2, v3);
            } else {
                // transposed single: vt[(b*768+col)][n]
                float vv[4] = {v0, v1, v2, v3};
#pragma unroll
                for (int e = 0; e < 4; e++) {
                    const int rr = row + (e >> 1) * 8;
                    const int cc = col + (e & 1);
                    const int bb = rr >> 10, nn = rr & 1023;
                    Oh[(size_t)(bb * DD + cc) * NN + nn] = __float2half_rn(vv[e]);
                }
            }
        }
    }
}

__global__ __launch_bounds__(256, 2) void qkv_mma_kernel(
    const __half* __restrict__ A, const __half* __restrict__ W,
    const float* __restrict__ bq, const float* __restrict__ bk,
    const float* __restrict__ bv,
    __half* __restrict__ q, __half* __restrict__ k, __half* __restrict__ vt) {
    const int z = blockIdx.z;
    const size_t ws = (size_t)z * DD * DD;
    if (z == 0)
        gemm_body(A, W + ws, bq, 3, nullptr, q);
    else if (z == 1)
        gemm_body(A, W + ws, bk, 3, nullptr, k);
    else
        gemm_body(A, W + ws, bv, 2, nullptr, vt);
}

__global__ __launch_bounds__(256, 2) void out_mma_kernel(
    const __half* __restrict__ A, const __half* __restrict__ W,
    const float* __restrict__ bias, float* __restrict__ C) {
    gemm_body(A, W, bias, 0, C, nullptr);
}

// ---------------------------------------------------------------------------
// fp16 tensor-core flash attention, quiet softmax.
// Raw-unit running max; P = ex2_f16x2(cvt_f16x2(S*SCALEQ - m*SCALEQ)):
// packed fp16 exp (HALF the MUFU ops; exp output IS the MMA fragment).
// Row sums Sigma-p computed by 8 extra MMAs against an all-ones B fragment
// (replaces 64 FADDs + 16 shuffles per iter).  Denominator = 1 + l (no 2^10
// offset; subnormal fp16 P is handled natively by HMMA).
// Warp tile 32q x 64k; Q fragments in registers; CTA = 4 warps = 128 q-rows;
// grid (8, 96); 2-stage pipeline, refill at top of loop.
// smem: Q 16K | 2 x (K 8K | V 8K) = 48K.
// ---------------------------------------------------------------------------
#define ATTN_STAGE 16384
#define ATTN_SMEM (16384 + 2 * ATTN_STAGE)   // 49152

__device__ __forceinline__ void attn_issue(
    uint32_t st, const __half* k_, const __half* vt_,
    int b, int hoff, int kt, int tid) {
    const int tok0 = b * NN + kt * 64;
#pragma unroll
    for (int i = 0; i < 4; i++) {   // K: 512 units (64 rows x 8u)
        const int t = tid + i * 128;
        const int r = (t >> 3) & 63, u = t & 7;
        cp16(st + swz8o(r, u), k_ + (size_t)(tok0 + r) * DD + hoff + u * 8);
    }
#pragma unroll
    for (int i = 0; i < 4; i++) {   // V: 512 units (64 d-rows x 8u)
        const int t = tid + i * 128;
        const int r = (t >> 3) & 63, u = t & 7;
        cp16(st + 8192 + swz8o(r, u),
             vt_ + (size_t)(b * DD + hoff + r) * NN + kt * 64 + u * 8);
    }
}

__global__ __launch_bounds__(128, 2) void attn_mma_kernel(
    const __half* __restrict__ q_, const __half* __restrict__ k_,
    const __half* __restrict__ vt_, __half* __restrict__ c_) {
    extern __shared__ char smem[];
    const uint32_t sb = s2u(smem);
    const int tid = threadIdx.x;
    const int wid = tid >> 5;
    const int lane = tid & 31;
    const int qt = blockIdx.x;        // 0..7 (128-row tiles)
    const int bh = blockIdx.y;        // 0..95
    const int b = bh / HH;
    const int h = bh - b * HH;
    const int hoff = h * HD;
    const int q0 = b * NN + qt * 128;
    const int strip = wid * 32;

    // Q tile: 1024 units (128 rows x 8u), + stage 0, one group
#pragma unroll
    for (int i = 0; i < 8; i++) {
        const int t = tid + i * 128;
        const int r = (t >> 3) & 127, u = t & 7;
        cp16(sb + swz8o(r, u), q_ + (size_t)(q0 + r) * DD + hoff + u * 8);
    }
    attn_issue(sb + 16384, k_, vt_, b, hoff, 0, tid);
    CP_COMMIT();

    const int a_r = lane & 15;
    const int a_uh = lane >> 4;
    const int b_r = ((lane >> 4) & 1) * 8 + (lane & 7);
    const int b_uh = (lane >> 3) & 1;

    // Wait for Q + stage0, hoist Q fragments into registers, start stage1
    CP_WAIT0();
    __syncthreads();
    uint32_t qf[4][2][4];
#pragma unroll
    for (int ks = 0; ks < 4; ks++)
#pragma unroll
        for (int fm = 0; fm < 2; fm++)
            ldm_x4(qf[ks][fm], sb + swz8o(strip + fm * 16 + a_r, ks * 2 + a_uh));
    attn_issue(sb + 16384 + ATTN_STAGE, k_, vt_, b, hoff, 1, tid);
    CP_COMMIT();

    const uint32_t ones2[2] = {0x3C003C00u, 0x3C003C00u};   // fp16 (1,1)

    float m_[4], l_[4];
#pragma unroll
    for (int j = 0; j < 4; j++) { m_[j] = -1e30f; l_[j] = 0.0f; }
    float ctx[2][8][4];
#pragma unroll
    for (int fm = 0; fm < 2; fm++)
#pragma unroll
        for (int fn = 0; fn < 8; fn++)
#pragma unroll
            for (int q = 0; q < 4; q++) ctx[fm][fn][q] = 0.0f;

    for (int kt = 0; kt < 16; kt++) {
        if (kt > 0) {
            CP_WAIT0();
            __syncthreads();
            // Refill the slot of kt-1 (all warps passed the barrier => done).
            if (kt + 1 < 16)
                attn_issue(sb + 16384 + ((kt + 1) & 1) * ATTN_STAGE,
                           k_, vt_, b, hoff, kt + 1, tid);
            CP_COMMIT();
        }
        const uint32_t st = sb + 16384 + (kt & 1) * ATTN_STAGE;

        // ---- S[32 q x 64 keys] = Q K^T (raw units) ----
        float S[2][8][4];
#pragma unroll
        for (int fm = 0; fm < 2; fm++)
#pragma unroll
            for (int fn = 0; fn < 8; fn++)
#pragma unroll
                for (int q = 0; q < 4; q++) S[fm][fn][q] = 0.0f;

#pragma unroll
        for (int ks = 0; ks < 4; ks++) {
            const int ub = ks * 2 + b_uh;
#pragma unroll
            for (int fn2 = 0; fn2 < 4; fn2++) {
                uint32_t k4[4];
                ldm_x4(k4, st + swz8o(fn2 * 16 + b_r, ub));
#pragma unroll
                for (int fm = 0; fm < 2; fm++) {
                    mma16816(S[fm][fn2 * 2 + 0], qf[ks][fm], &k4[0]);
                    mma16816(S[fm][fn2 * 2 + 1], qf[ks][fm], &k4[2]);
                }
            }
        }

        // ---- online quiet softmax: max reduce + ctx rescale (4 row groups) ----
        float mx[4] = {-1e30f, -1e30f, -1e30f, -1e30f};
#pragma unroll
        for (int fm = 0; fm < 2; fm++)
#pragma unroll
            for (int fn = 0; fn < 8; fn++) {
                mx[fm * 2 + 0] = fmaxf(mx[fm * 2 + 0], fmaxf(S[fm][fn][0], S[fm][fn][1]));
                mx[fm * 2 + 1] = fmaxf(mx[fm * 2 + 1], fmaxf(S[fm][fn][2], S[fm][fn][3]));
            }
        float corr[4], cc[4];
#pragma unroll
        for (int j = 0; j < 4; j++) {
            mx[j] = fmaxf(mx[j], __shfl_xor_sync(0xffffffffu, mx[j], 1));
            mx[j] = fmaxf(mx[j], __shfl_xor_sync(0xffffffffu, mx[j], 2));
            const float mn = fmaxf(m_[j], mx[j]);
            corr[j] = ex2((m_[j] - mn) * SCALEQ);
            m_[j] = mn;
            cc[j] = -mn * SCALEQ;
        }
#pragma unroll
        for (int fm = 0; fm < 2; fm++)
#pragma unroll
            for (int fn = 0; fn < 8; fn++) {
                ctx[fm][fn][0] *= corr[fm * 2];
                ctx[fm][fn][1] *= corr[fm * 2];
                ctx[fm][fn][2] *= corr[fm * 2 + 1];
                ctx[fm][fn][3] *= corr[fm * 2 + 1];
            }

        // ---- packed-fp16 exp + PV (+ row sums via ones-MMA) ----
        float lsum[2][4];
#pragma unroll
        for (int fm = 0; fm < 2; fm++)
#pragma unroll
            for (int q = 0; q < 4; q++) lsum[fm][q] = 0.0f;

#pragma unroll
        for (int kb = 0; kb < 4; kb++) {
            uint32_t pa[2][4];
#pragma unroll
            for (int fm = 0; fm < 2; fm++) {
                const float a0 = fmaf(S[fm][2 * kb][0], SCALEQ, cc[fm * 2]);
                const float a1 = fmaf(S[fm][2 * kb][1], SCALEQ, cc[fm * 2]);
                const float a2 = fmaf(S[fm][2 * kb][2], SCALEQ, cc[fm * 2 + 1]);
                const float a3 = fmaf(S[fm][2 * kb][3], SCALEQ, cc[fm * 2 + 1]);
                const float b0 = fmaf(S[fm][2 * kb + 1][0], SCALEQ, cc[fm * 2]);
                const float b1 = fmaf(S[fm][2 * kb + 1][1], SCALEQ, cc[fm * 2]);
                const float b2 = fmaf(S[fm][2 * kb + 1][2], SCALEQ, cc[fm * 2 + 1]);
                const float b3 = fmaf(S[fm][2 * kb + 1][3], SCALEQ, cc[fm * 2 + 1]);
                pa[fm][0] = h2ex2(cvt2h(a0, a1));
                pa[fm][1] = h2ex2(cvt2h(a2, a3));
                pa[fm][2] = h2ex2(cvt2h(b0, b1));
                pa[fm][3] = h2ex2(cvt2h(b2, b3));
                mma16816(lsum[fm], pa[fm], ones2);
            }
            const int ub = kb * 2 + b_uh;
#pragma unroll
            for (int fn2 = 0; fn2 < 4; fn2++) {
                uint32_t v4[4];
                ldm_x4(v4, st + 8192 + swz8o(fn2 * 16 + b_r, ub));
#pragma unroll
                for (int fm = 0; fm < 2; fm++) {
                    mma16816(ctx[fm][fn2 * 2 + 0], pa[fm], &v4[0]);
                    mma16816(ctx[fm][fn2 * 2 + 1], pa[fm], &v4[2]);
                }
            }
        }
#pragma unroll
        for (int fm = 0; fm < 2; fm++) {
            l_[fm * 2 + 0] = l_[fm * 2 + 0] * corr[fm * 2 + 0] + lsum[fm][0];
            l_[fm * 2 + 1] = l_[fm * 2 + 1] * corr[fm * 2 + 1] + lsum[fm][2];
        }
    }

    // ---- epilogue: out = ctx / (1 + l); emit half single ----
#pragma unroll
    for (int fm = 0; fm < 2; fm++) {
        const float inv0 = 1.0f / (1.0f + l_[fm * 2]);
        const float inv1 = 1.0f / (1.0f + l_[fm * 2 + 1]);
        const int rowA = q0 + strip + fm * 16 + (lane >> 2);
        const int rowB = rowA + 8;
#pragma unroll
        for (int fn = 0; fn < 8; fn++) {
            const int col = hoff + fn * 8 + (lane & 3) * 2;
            *reinterpret_cast<uint32_t*>(&c_[(size_t)rowA * DD + col]) =
                cvt2h(ctx[fm][fn][0] * inv0, ctx[fm][fn][1] * inv0);
            *reinterpret_cast<uint32_t*>(&c_[(size_t)rowB * DD + col]) =
                cvt2h(ctx[fm][fn][2] * inv1, ctx[fm][fn][3] * inv1);
        }
    }
}

// ---------------------------------------------------------------------------
// Launch
// ---------------------------------------------------------------------------
extern "C" void kernel_launch(void* const* d_in, const int* in_sizes, int n_in,
                              void* d_out, int out_size) {
    const float* x  = (const float*)d_in[0];
    const float* Wq = (const float*)d_in[1];
    const float* bq = (const float*)d_in[2];
    const float* Wk = (const float*)d_in[3];
    const float* bk = (const float*)d_in[4];
    const float* Wv = (const float*)d_in[5];
    const float* bv = (const float*)d_in[6];
    const float* Wo = (const float*)d_in[7];
    const float* bo = (const float*)d_in[8];
    float* out = (float*)d_out;
    (void)in_sizes; (void)n_in; (void)out_size;

    __half *xs, *q, *k, *vt, *c, *w;
    cudaGetSymbolAddress((void**)&xs, g_x);
    cudaGetSymbolAddress((void**)&q, g_q);
    cudaGetSymbolAddress((void**)&k, g_k);
    cudaGetSymbolAddress((void**)&vt, g_vt);
    cudaGetSymbolAddress((void**)&c, g_c);
    cudaGetSymbolAddress((void**)&w, g_w);

    cudaFuncSetAttribute(qkv_mma_kernel, cudaFuncAttributeMaxDynamicSharedMemorySize,
                         GEMM_SMEM);
    cudaFuncSetAttribute(out_mma_kernel, cudaFuncAttributeMaxDynamicSharedMemorySize,
                         GEMM_SMEM);
    cudaFuncSetAttribute(attn_mma_kernel, cudaFuncAttributeMaxDynamicSharedMemorySize,
                         ATTN_SMEM);

    const size_t ws = (size_t)DD * DD;

    convert_half_kernel<<<MM * DD / 8 / 256, 256>>>(x, xs);
    convert_wt_kernel<<<dim3(12, 12, 4), 256>>>(Wq, Wk, Wv, Wo, w);
    qkv_mma_kernel<<<dim3(6, 64, 3), 256, GEMM_SMEM>>>(xs, w, bq, bk, bv, q, k, vt);
    attn_mma_kernel<<<dim3(8, 96), 128, ATTN_SMEM>>>(q, k, vt, c);
    out_mma_kernel<<<dim3(6, 64), 256, GEMM_SMEM>>>(c, w + 3 * ws, bo, out);
}